// round 1
// baseline (speedup 1.0000x reference)
#include <cuda_runtime.h>
#include <math.h>

#define N_ROWS 32768
#define DIM    256
#define KCODES 1024

// ---------------- device scratch (no allocations allowed) ----------------
__device__ float g_S[(size_t)N_ROWS * KCODES];   // s[n,k] = |c_k|^2 - 2 x_n.c_k  (134 MB)
__device__ float g_c2[KCODES];
__device__ float g_probs[KCODES];                // sum over rows of softmax probs
__device__ float g_scal[2];                      // [0] = sum (q-x)^2, [1] = sum per-row sample-entropy

// ---------------- init: zero accumulators + codebook norms ----------------
__global__ void vq_init_kernel(const float* __restrict__ CB) {
    int gtid = blockIdx.x * blockDim.x + threadIdx.x;
    if (gtid < KCODES) g_probs[gtid] = 0.f;
    if (gtid < 2) g_scal[gtid] = 0.f;
    int wid = gtid >> 5;
    int lane = gtid & 31;
    if (wid < KCODES) {
        const float* c = CB + (size_t)wid * DIM;
        float s = 0.f;
        for (int i = lane; i < DIM; i += 32) { float v = c[i]; s += v * v; }
        #pragma unroll
        for (int o = 16; o; o >>= 1) s += __shfl_down_sync(0xffffffffu, s, o);
        if (lane == 0) g_c2[wid] = s;
    }
}

// ---------------- fp32 GEMM: s[n,k] = c2[k] - 2 * dot(x_n, c_k) ----------------
// 128x128 tile, BK=16, 256 threads, 8x8 microtile per thread
#define BM 128
#define BN 128
#define BK 16
__global__ __launch_bounds__(256, 2)
void vq_gemm_kernel(const float* __restrict__ X, const float* __restrict__ CB) {
    __shared__ __align__(16) float As[BK][BM + 4];
    __shared__ __align__(16) float Bs[BK][BN + 4];

    const int bn = blockIdx.x;          // code tile (0..7)
    const int bm = blockIdx.y;          // row tile  (0..255)
    const int tid = threadIdx.x;        // 0..255
    const int tx = tid & 15;            // code sub
    const int ty = tid >> 4;            // row sub

    float acc[8][8];
    #pragma unroll
    for (int i = 0; i < 8; i++)
        #pragma unroll
        for (int j = 0; j < 8; j++) acc[i][j] = 0.f;

    const float* Xp = X  + (size_t)(bm * BM) * DIM;
    const float* Cp = CB + (size_t)(bn * BN) * DIM;

    for (int k0 = 0; k0 < DIM; k0 += BK) {
        // load 128x16 of X and CB into smem (transposed), 2 float4 per array per thread
        #pragma unroll
        for (int i = 0; i < 2; i++) {
            int li  = tid + i * 256;        // 0..511
            int row = li >> 2;              // 0..127
            int c4  = (li & 3) * 4;         // 0,4,8,12
            float4 va = *(const float4*)(Xp + (size_t)row * DIM + k0 + c4);
            As[c4 + 0][row] = va.x; As[c4 + 1][row] = va.y;
            As[c4 + 2][row] = va.z; As[c4 + 3][row] = va.w;
            float4 vb = *(const float4*)(Cp + (size_t)row * DIM + k0 + c4);
            Bs[c4 + 0][row] = vb.x; Bs[c4 + 1][row] = vb.y;
            Bs[c4 + 2][row] = vb.z; Bs[c4 + 3][row] = vb.w;
        }
        __syncthreads();

        #pragma unroll
        for (int kk = 0; kk < BK; kk++) {
            float a[8], b[8];
            float4 a0 = *(const float4*)&As[kk][ty * 8];
            float4 a1 = *(const float4*)&As[kk][ty * 8 + 4];
            float4 b0 = *(const float4*)&Bs[kk][tx * 8];
            float4 b1 = *(const float4*)&Bs[kk][tx * 8 + 4];
            a[0]=a0.x; a[1]=a0.y; a[2]=a0.z; a[3]=a0.w;
            a[4]=a1.x; a[5]=a1.y; a[6]=a1.z; a[7]=a1.w;
            b[0]=b0.x; b[1]=b0.y; b[2]=b0.z; b[3]=b0.w;
            b[4]=b1.x; b[5]=b1.y; b[6]=b1.z; b[7]=b1.w;
            #pragma unroll
            for (int i = 0; i < 8; i++)
                #pragma unroll
                for (int j = 0; j < 8; j++)
                    acc[i][j] += a[i] * b[j];
        }
        __syncthreads();
    }

    // epilogue: s = c2[k] - 2*acc
    float c2v[8];
    #pragma unroll
    for (int j = 0; j < 8; j++) c2v[j] = g_c2[bn * BN + tx * 8 + j];

    #pragma unroll
    for (int i = 0; i < 8; i++) {
        int n = bm * BM + ty * 8 + i;
        float* outp = g_S + (size_t)n * KCODES + bn * BN + tx * 8;
        float4 v0, v1;
        v0.x = c2v[0] - 2.f * acc[i][0];
        v0.y = c2v[1] - 2.f * acc[i][1];
        v0.z = c2v[2] - 2.f * acc[i][2];
        v0.w = c2v[3] - 2.f * acc[i][3];
        v1.x = c2v[4] - 2.f * acc[i][4];
        v1.y = c2v[5] - 2.f * acc[i][5];
        v1.z = c2v[6] - 2.f * acc[i][6];
        v1.w = c2v[7] - 2.f * acc[i][7];
        *(float4*)(outp)     = v0;
        *(float4*)(outp + 4) = v1;
    }
}

// ---------------- per-row: argmin, softmax stats, gather, loss partials ----------------
#define ROWS_PER_BLOCK 32
__global__ __launch_bounds__(256)
void vq_row_kernel(const float* __restrict__ X, const float* __restrict__ CB,
                   float* __restrict__ out_q, float* __restrict__ out_idx) {
    __shared__ float s_ra[8], s_rb[8], s_rc[8];
    __shared__ int   s_ri[8];
    __shared__ float s_min, s_Z;
    __shared__ int   s_idx;

    const int t = threadIdx.x;       // 0..255
    const int lane = t & 31;
    const int wid = t >> 5;          // 0..7

    float pacc0 = 0.f, pacc1 = 0.f, pacc2 = 0.f, pacc3 = 0.f;
    float ent_sum = 0.f, lat_sum = 0.f;   // meaningful on thread 0 only

    for (int r = 0; r < ROWS_PER_BLOCK; r++) {
        const int n = blockIdx.x * ROWS_PER_BLOCK + r;
        const float* srow = g_S + (size_t)n * KCODES;
        float s0 = srow[t];
        float s1v = srow[t + 256];
        float s2 = srow[t + 512];
        float s3 = srow[t + 768];

        // local min (earliest index wins on ties)
        float mv = s0; int mi = t;
        if (s1v < mv) { mv = s1v; mi = t + 256; }
        if (s2  < mv) { mv = s2;  mi = t + 512; }
        if (s3  < mv) { mv = s3;  mi = t + 768; }

        #pragma unroll
        for (int o = 16; o; o >>= 1) {
            float ov = __shfl_down_sync(0xffffffffu, mv, o);
            int   oi = __shfl_down_sync(0xffffffffu, mi, o);
            if (ov < mv || (ov == mv && oi < mi)) { mv = ov; mi = oi; }
        }
        if (lane == 0) { s_ra[wid] = mv; s_ri[wid] = mi; }
        __syncthreads();
        if (wid == 0) {
            float v = (lane < 8) ? s_ra[lane] : 3.4e38f;
            int  ii = (lane < 8) ? s_ri[lane] : 0x7fffffff;
            #pragma unroll
            for (int o = 4; o; o >>= 1) {
                float ov = __shfl_down_sync(0xffffffffu, v, o);
                int   oi = __shfl_down_sync(0xffffffffu, ii, o);
                if (ov < v || (ov == v && oi < ii)) { v = ov; ii = oi; }
            }
            if (lane == 0) { s_min = v; s_idx = ii; }
        }
        __syncthreads();
        const float smin = s_min;
        const int idx = s_idx;

        // softmax numerator terms (temperature 0.01 -> *100 on distances)
        float d0 = s0 - smin, d1 = s1v - smin, d2 = s2 - smin, d3 = s3 - smin;
        float e0 = expf(-100.f * d0);
        float e1 = expf(-100.f * d1);
        float e2 = expf(-100.f * d2);
        float e3 = expf(-100.f * d3);
        float z  = e0 + e1 + e2 + e3;
        float s1sum = e0 * d0 + e1 * d1 + e2 * d2 + e3 * d3;

        // gather quantized row + exact latent contribution
        float cv = CB[(size_t)idx * DIM + t];
        float xv = X[(size_t)n * DIM + t];
        out_q[(size_t)n * DIM + t] = cv;
        float df = cv - xv;
        float d2sum = df * df;

        // combined block reduce of (z, s1sum, d2sum)
        #pragma unroll
        for (int o = 16; o; o >>= 1) {
            z     += __shfl_down_sync(0xffffffffu, z, o);
            s1sum += __shfl_down_sync(0xffffffffu, s1sum, o);
            d2sum += __shfl_down_sync(0xffffffffu, d2sum, o);
        }
        if (lane == 0) { s_ra[wid] = z; s_rb[wid] = s1sum; s_rc[wid] = d2sum; }
        __syncthreads();
        if (wid == 0) {
            float a = (lane < 8) ? s_ra[lane] : 0.f;
            float b = (lane < 8) ? s_rb[lane] : 0.f;
            float c = (lane < 8) ? s_rc[lane] : 0.f;
            #pragma unroll
            for (int o = 4; o; o >>= 1) {
                a += __shfl_down_sync(0xffffffffu, a, o);
                b += __shfl_down_sync(0xffffffffu, b, o);
                c += __shfl_down_sync(0xffffffffu, c, o);
            }
            if (lane == 0) {
                s_Z = a;
                ent_sum += 100.f * (b / a) + logf(a);  // per-row sample entropy
                lat_sum += c;
            }
        }
        __syncthreads();
        const float Z = s_Z;
        pacc0 += e0 / Z;
        pacc1 += e1 / Z;
        pacc2 += e2 / Z;
        pacc3 += e3 / Z;

        if (t == 0 && out_idx) out_idx[n] = (float)idx;
        __syncthreads();
    }

    atomicAdd(&g_probs[t],       pacc0);
    atomicAdd(&g_probs[t + 256], pacc1);
    atomicAdd(&g_probs[t + 512], pacc2);
    atomicAdd(&g_probs[t + 768], pacc3);
    if (t == 0) {
        atomicAdd(&g_scal[0], lat_sum);
        atomicAdd(&g_scal[1], ent_sum);
    }
}

// ---------------- finalize: avg-probs entropy + loss scalar ----------------
__global__ void vq_finalize_kernel(float* __restrict__ out_loss) {
    __shared__ float warp_s[32];
    const int t = threadIdx.x;        // 0..1023
    const int lane = t & 31;
    const int wid = t >> 5;

    float p = g_probs[t] * (1.0f / (float)N_ROWS);
    float contrib = -p * logf(p + 1e-5f);
    #pragma unroll
    for (int o = 16; o; o >>= 1) contrib += __shfl_down_sync(0xffffffffu, contrib, o);
    if (lane == 0) warp_s[wid] = contrib;
    __syncthreads();
    if (wid == 0) {
        float v = warp_s[lane];   // 32 warps exactly
        #pragma unroll
        for (int o = 16; o; o >>= 1) v += __shfl_down_sync(0xffffffffu, v, o);
        if (lane == 0 && out_loss) {
            float avg_entropy = v;
            float sample_entropy = g_scal[1] * (1.0f / (float)N_ROWS);
            float mean_lat = g_scal[0] * (1.0f / ((float)N_ROWS * (float)DIM));
            float ent_loss = sample_entropy - avg_entropy;
            float loss = 1.25f * mean_lat + 0.1f * ent_loss;
            *out_loss = loss;
        }
    }
}

// ---------------- launch ----------------
extern "C" void kernel_launch(void* const* d_in, const int* in_sizes, int n_in,
                              void* d_out, int out_size) {
    const float* X  = (const float*)d_in[0];   // [32768, 256]
    const float* CB = (const float*)d_in[1];   // [1024, 256]
    float* out = (float*)d_out;

    float* out_q    = out;
    float* out_loss = (out_size >= N_ROWS * DIM + 1) ? (out + (size_t)N_ROWS * DIM) : nullptr;
    float* out_idx  = (out_size >= N_ROWS * DIM + 1 + N_ROWS) ? (out + (size_t)N_ROWS * DIM + 1) : nullptr;

    vq_init_kernel<<<128, 256>>>(CB);
    dim3 g(KCODES / BN, N_ROWS / BM);
    vq_gemm_kernel<<<g, 256>>>(X, CB);
    vq_row_kernel<<<N_ROWS / ROWS_PER_BLOCK, 256>>>(X, CB, out_q, out_idx);
    vq_finalize_kernel<<<1, 1024>>>(out_loss);
}